// round 1
// baseline (speedup 1.0000x reference)
#include <cuda_runtime.h>

#define CAPN 134
#define SEQN 144
#define INVN 16
#define ESP  1072
#define EFT  64
#define BZN  32

// ---------------- device-global precomputed tables (tiny) ----------------
__device__ int   g_rowptr[CAPN + 1];
__device__ int   g_cols[ESP];
__device__ float g_invdeg[CAPN];
__device__ float g_M1[256], g_M2[256], g_B1[256], g_B2[256];
__device__ float g_Wt[16 * 5 * 16];     // [i][k][j]
__device__ float g_bias[SEQN * 16];     // [s][j]

// ---------------- prep: CSR + composite weights ----------------
__global__ void prep_kernel(const int* __restrict__ ge, const int* __restrict__ fe,
                            const float* __restrict__ gWl, const float* __restrict__ gbl,
                            const float* __restrict__ gWr,
                            const float* __restrict__ fbl,
                            const float* __restrict__ c1w, const float* __restrict__ c2w,
                            const float* __restrict__ fcw, const float* __restrict__ fcb)
{
    __shared__ int   cnt[CAPN];
    __shared__ int   base[CAPN + 1];
    __shared__ int   fill[CAPN];
    __shared__ int   fcnt[256];
    __shared__ int   fdeg[INVN];
    __shared__ float Afn[256];
    int tid = threadIdx.x;

    if (tid < CAPN) cnt[tid] = 0;
    if (tid < 256)  fcnt[tid] = 0;
    if (tid < INVN) fdeg[tid] = 0;
    __syncthreads();

    for (int e = tid; e < ESP; e += blockDim.x) atomicAdd(&cnt[ge[ESP + e]], 1);
    for (int e = tid; e < EFT; e += blockDim.x) {
        int d = fe[EFT + e], s = fe[e];
        atomicAdd(&fcnt[d * INVN + s], 1);
        atomicAdd(&fdeg[d], 1);
    }
    __syncthreads();

    if (tid == 0) {
        int run = 0;
        for (int i = 0; i < CAPN; i++) { base[i] = run; run += cnt[i]; }
        base[CAPN] = run;
    }
    __syncthreads();
    if (tid < CAPN) fill[tid] = base[tid];
    __syncthreads();
    for (int e = tid; e < ESP; e += blockDim.x) {
        int d = ge[ESP + e];
        int pos = atomicAdd(&fill[d], 1);
        g_cols[pos] = ge[e];             // src node of this edge
    }
    if (tid < CAPN)  g_invdeg[tid] = 1.0f / fmaxf((float)cnt[tid], 1.0f);
    if (tid <= CAPN) g_rowptr[tid] = base[tid];
    if (tid < 256) {
        int i = tid >> 4;
        Afn[tid] = (float)fcnt[tid] / fmaxf((float)fdeg[i], 1.0f);  // Afn[dst][src]
    }
    __syncthreads();

    if (tid < 256) {
        int i = tid >> 4, j = tid & 15;
        float m1 = 0.f, m2 = 0.f, b1 = 0.f;
        for (int o = 0; o < 16; o++) {
            m1 += gWl[i * 16 + o] * fcw[o * 16 + j];          // W1 = fcw rows 0..15
            m2 += gWr[i * 16 + o] * fcw[o * 16 + j];
            b1 += Afn[o * 16 + i] * fcw[(16 + o) * 16 + j];   // A_f^T @ W2
        }
        g_M1[tid] = m1; g_M2[tid] = m2; g_B1[tid] = b1;
        g_B2[tid] = fcw[(16 + i) * 16 + j];                    // W2
        for (int k = 0; k < 5; k++) {
            float wt = 0.f;
            for (int o = 0; o < 16; o++) {
                float wm = c2w[(o * 16 + i) * 5 + k];
                if (k >= 1 && k <= 3) wm += c1w[(o * 16 + i) * 3 + (k - 1)];
                wt += wm * fcw[(32 + o) * 16 + j];             // W3
            }
            g_Wt[(i * 5 + k) * 16 + j] = wt;
        }
    }
    for (int idx = tid; idx < SEQN * 16; idx += blockDim.x) {
        int s = idx >> 4, j = idx & 15;
        float cs = 0.f, gb = 0.f;
        for (int i = 0; i < 16; i++) cs += fcw[(16 + i) * 16 + j];
        for (int o = 0; o < 16; o++) gb += gbl[o] * fcw[o * 16 + j];
        g_bias[idx] = fcb[j] + fbl[s] * cs + gb;
    }
}

// ---------------- fused main kernel ----------------
struct SM {
    float tile[2][SEQN][17];   // padded: stride 17 -> conflict-free scalar access
    float macc[2][SEQN][17];
    float P[2][2][SEQN][16];   // [item][P1/P2][t][j]
    float W[2][8][SEQN];       // staged Wl/Wr chunk: [wl/wr][tt][s]
    float M1[256], M2[256], B1[256], B2[256];
    float Wt[16 * 5 * 16];
    float bias[SEQN][17];
};

__global__ void __launch_bounds__(288, 2)
main_kernel(const float* __restrict__ src,
            const float* __restrict__ fWl, const float* __restrict__ fWr,
            float* __restrict__ out)
{
    extern __shared__ SM smx[];
    SM& s = smx[0];
    const int tid = threadIdx.x;
    const int item0 = blockIdx.x * 2;

    // ---- phase 0: stage constants ----
    if (tid < 256) {
        s.M1[tid] = g_M1[tid]; s.M2[tid] = g_M2[tid];
        s.B1[tid] = g_B1[tid]; s.B2[tid] = g_B2[tid];
    }
    for (int idx = tid; idx < 16 * 5 * 16; idx += 288) s.Wt[idx] = g_Wt[idx];
    for (int idx = tid; idx < SEQN * 16; idx += 288) s.bias[idx >> 4][idx & 15] = g_bias[idx];

    // ---- phase 1: load own tiles (2 items x 144 x 16) ----
    for (int idx = tid; idx < 2 * SEQN * 4; idx += 288) {
        int it = idx / (SEQN * 4);
        int rr = idx % (SEQN * 4);
        int ss = rr >> 2, iq = (rr & 3) * 4;
        float4 v = *(const float4*)(src + ((size_t)(item0 + it) * SEQN + ss) * 16 + iq);
        s.tile[it][ss][iq + 0] = v.x; s.tile[it][ss][iq + 1] = v.y;
        s.tile[it][ss][iq + 2] = v.z; s.tile[it][ss][iq + 3] = v.w;
    }
    __syncthreads();

    // ---- phase 2: spatial neighbor-mean gather (288 thr = 2 items x 144 s) ----
    {
        int it = tid / SEQN, ss = tid % SEQN;
        int item = item0 + it;
        int b = item / CAPN, c = item % CAPN;
        float acc[16];
        #pragma unroll
        for (int i = 0; i < 16; i++) acc[i] = 0.f;
        int p0 = g_rowptr[c], p1 = g_rowptr[c + 1];
        for (int p = p0; p < p1; p++) {
            int cp = g_cols[p];
            const float4* row = (const float4*)(src + ((size_t)(b * CAPN + cp) * SEQN + ss) * 16);
            float4 v0 = row[0], v1 = row[1], v2 = row[2], v3 = row[3];
            acc[0] += v0.x; acc[1] += v0.y; acc[2] += v0.z; acc[3] += v0.w;
            acc[4] += v1.x; acc[5] += v1.y; acc[6] += v1.z; acc[7] += v1.w;
            acc[8] += v2.x; acc[9] += v2.y; acc[10] += v2.z; acc[11] += v2.w;
            acc[12] += v3.x; acc[13] += v3.y; acc[14] += v3.z; acc[15] += v3.w;
        }
        float sc = g_invdeg[c];
        #pragma unroll
        for (int i = 0; i < 16; i++) s.macc[it][ss][i] = acc[i] * sc;
    }

    // ---- phase 3: P1 = tile@B1, P2 = tile@B2 (288 thr = 2 items x 144 t) ----
    {
        int it = tid / SEQN, t = tid % SEQN;
        float x[16];
        #pragma unroll
        for (int i = 0; i < 16; i++) x[i] = s.tile[it][t][i];
        float p1v[16], p2v[16];
        #pragma unroll
        for (int j = 0; j < 16; j++) { p1v[j] = 0.f; p2v[j] = 0.f; }
        #pragma unroll
        for (int i = 0; i < 16; i++) {
            float xv = x[i];
            #pragma unroll
            for (int j = 0; j < 16; j++) {
                p1v[j] += xv * s.B1[i * 16 + j];
                p2v[j] += xv * s.B2[i * 16 + j];
            }
        }
        #pragma unroll
        for (int q = 0; q < 4; q++) {
            *(float4*)&s.P[it][0][t][q * 4] = make_float4(p1v[q*4], p1v[q*4+1], p1v[q*4+2], p1v[q*4+3]);
            *(float4*)&s.P[it][1][t][q * 4] = make_float4(p2v[q*4], p2v[q*4+1], p2v[q*4+2], p2v[q*4+3]);
        }
    }
    __syncthreads();

    // ---- phase 4: per-thread 4s x 4j output tile ----
    const int it = tid / 144;
    const int r  = tid % 144;
    const int jg = r / 36, sg = r % 36;
    const int j0 = jg * 4;
    int srow[4];
    #pragma unroll
    for (int a = 0; a < 4; a++) srow[a] = sg + 36 * a;

    float acc[4][4];
    #pragma unroll
    for (int a = 0; a < 4; a++)
        #pragma unroll
        for (int bb = 0; bb < 4; bb++)
            acc[a][bb] = s.bias[srow[a]][j0 + bb] + s.tile[it][srow[a]][j0 + bb];

    // spatial (macc@M1) + residual-ish (tile@M2)
    #pragma unroll
    for (int i = 0; i < 16; i++) {
        float m1j[4], m2j[4];
        #pragma unroll
        for (int bb = 0; bb < 4; bb++) { m1j[bb] = s.M1[i * 16 + j0 + bb]; m2j[bb] = s.M2[i * 16 + j0 + bb]; }
        #pragma unroll
        for (int a = 0; a < 4; a++) {
            float tv = s.tile[it][srow[a]][i];
            float mv = s.macc[it][srow[a]][i];
            #pragma unroll
            for (int bb = 0; bb < 4; bb++) acc[a][bb] += tv * m2j[bb] + mv * m1j[bb];
        }
    }

    // temporal: merged width-5 conv with composite weights Wt[i][k][j]
    #pragma unroll
    for (int k = 0; k < 5; k++) {
        #pragma unroll
        for (int i = 0; i < 16; i++) {
            float wt[4];
            #pragma unroll
            for (int bb = 0; bb < 4; bb++) wt[bb] = s.Wt[(i * 5 + k) * 16 + j0 + bb];
            #pragma unroll
            for (int a = 0; a < 4; a++) {
                int row = srow[a] + k - 2;
                if (row >= 0 && row < SEQN) {
                    float tv = s.tile[it][row][i];
                    #pragma unroll
                    for (int bb = 0; bb < 4; bb++) acc[a][bb] += tv * wt[bb];
                }
            }
        }
    }

    // feature seq-mix: acc[s,j] += sum_t Wl[t,s]*P1[t,j] + Wr[t,s]*P2[t,j]
    for (int tc = 0; tc < SEQN; tc += 8) {
        __syncthreads();   // protect s.W reuse
        for (int q = tid; q < 576; q += 288) {
            int w = q / 288; int rr2 = q % 288;
            int tt = rr2 / 36; int s4 = (rr2 % 36) * 4;
            const float* Wg = w ? fWr : fWl;
            float4 v = *(const float4*)(Wg + (tc + tt) * SEQN + s4);
            *(float4*)&s.W[w][tt][s4] = v;
        }
        __syncthreads();
        #pragma unroll
        for (int tt = 0; tt < 8; tt++) {
            int t = tc + tt;
            float4 p1 = *(const float4*)&s.P[it][0][t][j0];
            float4 p2 = *(const float4*)&s.P[it][1][t][j0];
            float wl[4], wr[4];
            #pragma unroll
            for (int a = 0; a < 4; a++) { wl[a] = s.W[0][tt][srow[a]]; wr[a] = s.W[1][tt][srow[a]]; }
            #pragma unroll
            for (int a = 0; a < 4; a++) {
                acc[a][0] += wl[a] * p1.x + wr[a] * p2.x;
                acc[a][1] += wl[a] * p1.y + wr[a] * p2.y;
                acc[a][2] += wl[a] * p1.z + wr[a] * p2.z;
                acc[a][3] += wl[a] * p1.w + wr[a] * p2.w;
            }
        }
    }

    // ---- write out: out = src + everything ----
    const size_t obase = (size_t)(item0 + it) * SEQN * 16;
    #pragma unroll
    for (int a = 0; a < 4; a++) {
        *(float4*)(out + obase + (size_t)srow[a] * 16 + j0) =
            make_float4(acc[a][0], acc[a][1], acc[a][2], acc[a][3]);
    }
}

// ---------------- launch ----------------
extern "C" void kernel_launch(void* const* d_in, const int* in_sizes, int n_in,
                              void* d_out, int out_size)
{
    const float* src = (const float*)d_in[0];
    const int*   ge  = (const int*)d_in[1];
    const int*   fe  = (const int*)d_in[2];
    const float* gWl = (const float*)d_in[3];
    const float* gbl = (const float*)d_in[4];
    const float* gWr = (const float*)d_in[5];
    const float* fWl = (const float*)d_in[6];
    const float* fbl = (const float*)d_in[7];
    const float* fWr = (const float*)d_in[8];
    const float* c1w = (const float*)d_in[9];
    const float* c2w = (const float*)d_in[10];
    const float* fcw = (const float*)d_in[11];
    const float* fcb = (const float*)d_in[12];
    float* out = (float*)d_out;

    cudaFuncSetAttribute(main_kernel, cudaFuncAttributeMaxDynamicSharedMemorySize,
                         (int)sizeof(SM));

    prep_kernel<<<1, 256>>>(ge, fe, gWl, gbl, gWr, fbl, c1w, c2w, fcw, fcb);
    main_kernel<<<(BZN * CAPN) / 2, 288, sizeof(SM)>>>(src, fWl, fWr, out);
}

// round 2
// speedup vs baseline: 1.0077x; 1.0077x over previous
#include <cuda_runtime.h>

#define CAPN 134
#define SEQN 144
#define INVN 16
#define ESP  1072
#define EFT  64
#define BZN  32

// ---------------- device-global precomputed tables (tiny) ----------------
__device__ int   g_rowptr[CAPN + 1];
__device__ int   g_cols[ESP];
__device__ float g_invdeg[CAPN];
__device__ float g_M1[256], g_M2[256], g_B1[256], g_B2[256];
__device__ float g_Wt[16 * 5 * 16];     // [i][k][j]
__device__ float g_bias[SEQN * 16];     // [s][j]

// ---------------- prep: CSR + composite weights ----------------
__global__ void prep_kernel(const int* __restrict__ ge, const int* __restrict__ fe,
                            const float* __restrict__ gWl, const float* __restrict__ gbl,
                            const float* __restrict__ gWr,
                            const float* __restrict__ fbl,
                            const float* __restrict__ c1w, const float* __restrict__ c2w,
                            const float* __restrict__ fcw, const float* __restrict__ fcb)
{
    __shared__ int   cnt[CAPN];
    __shared__ int   base[CAPN + 1];
    __shared__ int   fill[CAPN];
    __shared__ int   fcnt[256];
    __shared__ int   fdeg[INVN];
    __shared__ float Afn[256];
    int tid = threadIdx.x;

    if (tid < CAPN) cnt[tid] = 0;
    if (tid < 256)  fcnt[tid] = 0;
    if (tid < INVN) fdeg[tid] = 0;
    __syncthreads();

    for (int e = tid; e < ESP; e += blockDim.x) atomicAdd(&cnt[ge[ESP + e]], 1);
    for (int e = tid; e < EFT; e += blockDim.x) {
        int d = fe[EFT + e], s = fe[e];
        atomicAdd(&fcnt[d * INVN + s], 1);
        atomicAdd(&fdeg[d], 1);
    }
    __syncthreads();

    if (tid == 0) {
        int run = 0;
        for (int i = 0; i < CAPN; i++) { base[i] = run; run += cnt[i]; }
        base[CAPN] = run;
    }
    __syncthreads();
    if (tid < CAPN) fill[tid] = base[tid];
    __syncthreads();
    for (int e = tid; e < ESP; e += blockDim.x) {
        int d = ge[ESP + e];
        int pos = atomicAdd(&fill[d], 1);
        g_cols[pos] = ge[e];             // src node of this edge
    }
    if (tid < CAPN)  g_invdeg[tid] = 1.0f / fmaxf((float)cnt[tid], 1.0f);
    if (tid <= CAPN) g_rowptr[tid] = base[tid];
    if (tid < 256) {
        int i = tid >> 4;
        Afn[tid] = (float)fcnt[tid] / fmaxf((float)fdeg[i], 1.0f);  // Afn[dst][src]
    }
    __syncthreads();

    if (tid < 256) {
        int i = tid >> 4, j = tid & 15;
        float m1 = 0.f, m2 = 0.f, b1 = 0.f;
        for (int o = 0; o < 16; o++) {
            m1 += gWl[i * 16 + o] * fcw[o * 16 + j];          // W1 = fcw rows 0..15
            m2 += gWr[i * 16 + o] * fcw[o * 16 + j];
            b1 += Afn[o * 16 + i] * fcw[(16 + o) * 16 + j];   // A_f^T @ W2
        }
        g_M1[tid] = m1; g_M2[tid] = m2; g_B1[tid] = b1;
        g_B2[tid] = fcw[(16 + i) * 16 + j];                    // W2
        for (int k = 0; k < 5; k++) {
            float wt = 0.f;
            for (int o = 0; o < 16; o++) {
                float wm = c2w[(o * 16 + i) * 5 + k];
                if (k >= 1 && k <= 3) wm += c1w[(o * 16 + i) * 3 + (k - 1)];
                wt += wm * fcw[(32 + o) * 16 + j];             // W3
            }
            g_Wt[(i * 5 + k) * 16 + j] = wt;
        }
    }
    for (int idx = tid; idx < SEQN * 16; idx += blockDim.x) {
        int s = idx >> 4, j = idx & 15;
        float cs = 0.f, gb = 0.f;
        for (int i = 0; i < 16; i++) cs += fcw[(16 + i) * 16 + j];
        for (int o = 0; o < 16; o++) gb += gbl[o] * fcw[o * 16 + j];
        g_bias[idx] = fcb[j] + fbl[s] * cs + gb;
    }
}

// ---------------- fused main kernel: 4 items/block ----------------
// tile rows padded +2 each side (zero) to kill conv boundary predicates.
// stride 20 floats keeps float4 16B-aligned AND bank-conflict-free.
#define TS 20
struct SM {
    float tile[4][SEQN + 4][TS];   // 47,360 B  (rows 0..1 and 146..147 are zero pad)
    float macc[4][SEQN][TS];       // 46,080 B
    float P[4][2][SEQN][16];       // 73,728 B  [item][P1/P2][t][j]
    float W[2][16][SEQN];          // 18,432 B  staged Wl/Wr chunk
    float M1[256], M2[256], B1[256], B2[256];  // 4,096 B
    float Wt[16 * 5 * 16];         // 5,120 B
    float bias[SEQN][16];          // 9,216 B
};

#define FMA4(ACC, S, V) { (ACC)[0] += (S)*(V).x; (ACC)[1] += (S)*(V).y; \
                          (ACC)[2] += (S)*(V).z; (ACC)[3] += (S)*(V).w; }

__global__ void __launch_bounds__(288, 1)
main_kernel(const float* __restrict__ src,
            const float* __restrict__ fWl, const float* __restrict__ fWr,
            float* __restrict__ out)
{
    extern __shared__ SM smx[];
    SM& s = smx[0];
    const int tid = threadIdx.x;
    const int item0 = blockIdx.x * 4;

    // ---- phase 0: stage constants ----
    if (tid < 256) {
        s.M1[tid] = g_M1[tid]; s.M2[tid] = g_M2[tid];
        s.B1[tid] = g_B1[tid]; s.B2[tid] = g_B2[tid];
    }
    for (int idx = tid; idx < 16 * 5 * 16; idx += 288) s.Wt[idx] = g_Wt[idx];
    for (int idx = tid; idx < SEQN * 16; idx += 288)
        s.bias[idx >> 4][idx & 15] = g_bias[idx];

    // ---- phase 1: zero pads + load 4 tiles ----
    for (int idx = tid; idx < 4 * 4 * TS; idx += 288) {
        int it = idx / (4 * TS); int rr = idx % (4 * TS);
        int pr = rr / TS, cc = rr % TS;
        int row = (pr < 2) ? pr : (SEQN + pr);      // rows 0,1,146,147
        s.tile[it][row][cc] = 0.f;
    }
    for (int idx = tid; idx < 4 * SEQN * 4; idx += 288) {
        int it = idx / (SEQN * 4);
        int rr = idx % (SEQN * 4);
        int ss = rr >> 2, iq = (rr & 3) * 4;
        *(float4*)&s.tile[it][ss + 2][iq] =
            *(const float4*)(src + ((size_t)(item0 + it) * SEQN + ss) * 16 + iq);
    }
    __syncthreads();

    // ---- phase 2: spatial neighbor-mean gather (576 slots / 288 thr) ----
    for (int q = 0; q < 2; q++) {
        int slot = tid + 288 * q;
        int it = slot / SEQN, ss = slot % SEQN;
        int item = item0 + it;
        int b = item / CAPN, c = item % CAPN;
        float acc[16];
        #pragma unroll
        for (int i = 0; i < 16; i++) acc[i] = 0.f;
        int p0 = g_rowptr[c], p1 = g_rowptr[c + 1];
        for (int p = p0; p < p1; p++) {
            int cp = g_cols[p];
            const float4* row = (const float4*)(src + ((size_t)(b * CAPN + cp) * SEQN + ss) * 16);
            float4 v0 = row[0], v1 = row[1], v2 = row[2], v3 = row[3];
            acc[0] += v0.x; acc[1] += v0.y; acc[2] += v0.z; acc[3] += v0.w;
            acc[4] += v1.x; acc[5] += v1.y; acc[6] += v1.z; acc[7] += v1.w;
            acc[8] += v2.x; acc[9] += v2.y; acc[10] += v2.z; acc[11] += v2.w;
            acc[12] += v3.x; acc[13] += v3.y; acc[14] += v3.z; acc[15] += v3.w;
        }
        float sc = g_invdeg[c];
        #pragma unroll
        for (int qq = 0; qq < 4; qq++)
            *(float4*)&s.macc[it][ss][qq * 4] =
                make_float4(acc[qq*4]*sc, acc[qq*4+1]*sc, acc[qq*4+2]*sc, acc[qq*4+3]*sc);
    }

    // ---- phase 3: P1 = tile@B1, P2 = tile@B2 (576 rows / 288 thr) ----
    for (int q = 0; q < 2; q++) {
        int slot = tid + 288 * q;
        int it = slot / SEQN, t = slot % SEQN;
        float x[16];
        #pragma unroll
        for (int iq = 0; iq < 16; iq += 4) {
            float4 v = *(const float4*)&s.tile[it][t + 2][iq];
            x[iq] = v.x; x[iq+1] = v.y; x[iq+2] = v.z; x[iq+3] = v.w;
        }
        float p1v[16], p2v[16];
        #pragma unroll
        for (int j = 0; j < 16; j++) { p1v[j] = 0.f; p2v[j] = 0.f; }
        #pragma unroll
        for (int i = 0; i < 16; i++) {
            float xv = x[i];
            #pragma unroll
            for (int j = 0; j < 16; j++) {
                p1v[j] += xv * s.B1[i * 16 + j];
                p2v[j] += xv * s.B2[i * 16 + j];
            }
        }
        #pragma unroll
        for (int qq = 0; qq < 4; qq++) {
            *(float4*)&s.P[it][0][t][qq*4] = make_float4(p1v[qq*4], p1v[qq*4+1], p1v[qq*4+2], p1v[qq*4+3]);
            *(float4*)&s.P[it][1][t][qq*4] = make_float4(p2v[qq*4], p2v[qq*4+1], p2v[qq*4+2], p2v[qq*4+3]);
        }
    }
    __syncthreads();

    // ---- phase 4: per-thread 2 items x 4 rows x 4 j ----
    const int sel = tid / 144;          // 0: items 0,1   1: items 2,3
    const int r   = tid % 144;
    const int jg  = r / 36, sg = r % 36;
    const int j0  = jg * 4;
    const int itb = sel * 2;
    int srow[4];
    #pragma unroll
    for (int a = 0; a < 4; a++) srow[a] = sg + 36 * a;

    float acc[2][4][4];
    #pragma unroll
    for (int u = 0; u < 2; u++)
        #pragma unroll
        for (int a = 0; a < 4; a++) {
            float4 bv = *(const float4*)&s.bias[srow[a]][j0];
            float4 tv = *(const float4*)&s.tile[itb + u][srow[a] + 2][j0];
            acc[u][a][0] = bv.x + tv.x; acc[u][a][1] = bv.y + tv.y;
            acc[u][a][2] = bv.z + tv.z; acc[u][a][3] = bv.w + tv.w;
        }

    // spatial: macc@M1 + tile@M2, i vectorized
    #pragma unroll 1
    for (int iq = 0; iq < 16; iq += 4) {
        float4 m1v[4], m2v[4];
        #pragma unroll
        for (int ii = 0; ii < 4; ii++) {
            m1v[ii] = *(const float4*)&s.M1[(iq + ii) * 16 + j0];
            m2v[ii] = *(const float4*)&s.M2[(iq + ii) * 16 + j0];
        }
        #pragma unroll
        for (int u = 0; u < 2; u++) {
            const int it = itb + u;
            #pragma unroll
            for (int a = 0; a < 4; a++) {
                float4 tv = *(const float4*)&s.tile[it][srow[a] + 2][iq];
                float4 mv = *(const float4*)&s.macc[it][srow[a]][iq];
                float tvv[4], mvv[4];
                *(float4*)tvv = tv; *(float4*)mvv = mv;
                #pragma unroll
                for (int ii = 0; ii < 4; ii++) {
                    FMA4(acc[u][a], tvv[ii], m2v[ii]);
                    FMA4(acc[u][a], mvv[ii], m1v[ii]);
                }
            }
        }
    }

    // temporal: merged width-5 conv, zero-padded rows -> no predicates
    #pragma unroll 1
    for (int k = 0; k < 5; k++) {
        #pragma unroll 1
        for (int iq = 0; iq < 16; iq += 4) {
            float4 wtv[4];
            #pragma unroll
            for (int ii = 0; ii < 4; ii++)
                wtv[ii] = *(const float4*)&s.Wt[((iq + ii) * 5 + k) * 16 + j0];
            #pragma unroll
            for (int u = 0; u < 2; u++) {
                const int it = itb + u;
                #pragma unroll
                for (int a = 0; a < 4; a++) {
                    float4 tv = *(const float4*)&s.tile[it][srow[a] + k][iq];
                    float tvv[4];
                    *(float4*)tvv = tv;
                    #pragma unroll
                    for (int ii = 0; ii < 4; ii++)
                        FMA4(acc[u][a], tvv[ii], wtv[ii]);
                }
            }
        }
    }

    // feature seq-mix: acc[s,j] += sum_t Wl[t,s]*P1[t,j] + Wr[t,s]*P2[t,j]
    #pragma unroll 1
    for (int tc = 0; tc < SEQN; tc += 16) {
        __syncthreads();   // protect s.W reuse (first iter: also fences phases 2/3... redundant but cheap)
        for (int q = tid; q < 1152; q += 288) {
            int w = q / 576; int rr2 = q % 576;
            int tt = rr2 / 36; int s4 = (rr2 % 36) * 4;
            const float* Wg = w ? fWr : fWl;
            *(float4*)&s.W[w][tt][s4] = *(const float4*)(Wg + (tc + tt) * SEQN + s4);
        }
        __syncthreads();
        #pragma unroll 4
        for (int tt = 0; tt < 16; tt++) {
            const int t = tc + tt;
            float wl[4], wr[4];
            #pragma unroll
            for (int a = 0; a < 4; a++) { wl[a] = s.W[0][tt][srow[a]]; wr[a] = s.W[1][tt][srow[a]]; }
            #pragma unroll
            for (int u = 0; u < 2; u++) {
                float4 p1 = *(const float4*)&s.P[itb + u][0][t][j0];
                float4 p2 = *(const float4*)&s.P[itb + u][1][t][j0];
                #pragma unroll
                for (int a = 0; a < 4; a++) {
                    FMA4(acc[u][a], wl[a], p1);
                    FMA4(acc[u][a], wr[a], p2);
                }
            }
        }
    }

    // ---- write out ----
    #pragma unroll
    for (int u = 0; u < 2; u++) {
        const size_t obase = (size_t)(item0 + itb + u) * SEQN * 16;
        #pragma unroll
        for (int a = 0; a < 4; a++)
            *(float4*)(out + obase + (size_t)srow[a] * 16 + j0) =
                make_float4(acc[u][a][0], acc[u][a][1], acc[u][a][2], acc[u][a][3]);
    }
}

// ---------------- launch ----------------
extern "C" void kernel_launch(void* const* d_in, const int* in_sizes, int n_in,
                              void* d_out, int out_size)
{
    const float* src = (const float*)d_in[0];
    const int*   ge  = (const int*)d_in[1];
    const int*   fe  = (const int*)d_in[2];
    const float* gWl = (const float*)d_in[3];
    const float* gbl = (const float*)d_in[4];
    const float* gWr = (const float*)d_in[5];
    const float* fWl = (const float*)d_in[6];
    const float* fbl = (const float*)d_in[7];
    const float* fWr = (const float*)d_in[8];
    const float* c1w = (const float*)d_in[9];
    const float* c2w = (const float*)d_in[10];
    const float* fcw = (const float*)d_in[11];
    const float* fcb = (const float*)d_in[12];
    float* out = (float*)d_out;

    cudaFuncSetAttribute(main_kernel, cudaFuncAttributeMaxDynamicSharedMemorySize,
                         (int)sizeof(SM));

    prep_kernel<<<1, 256>>>(ge, fe, gWl, gbl, gWr, fbl, c1w, c2w, fcw, fcb);
    main_kernel<<<(BZN * CAPN) / 4, 288, sizeof(SM)>>>(src, fWl, fWr, out);
}